// round 2
// baseline (speedup 1.0000x reference)
#include <cuda_runtime.h>
#include <cfloat>
#include <cstdint>

#define BB 8
#define CC 3
#define HH 1080
#define WW 1920
#define KK 256
#define NBASIS 25
#define GBINS 4096          // power of two: x*4096.0f is EXACT in fp32
#define NSEG (KK + 1)       // 257 extended segments
#define PIX_PER_BATCH (CC * HH * WW)   // 6,220,800

__device__ float2 gBins[BB * GBINS];   // (a,b) pure bins, or NaN-payload(k0) kinked bins
__device__ float4 gSegs[BB * NSEG];    // (Elo, Ehi, a, b) exact segments

// ---------------------------------------------------------------------------
// Table builder: grid (BB, 17), 256 threads.
//   Every block recomputes the curve (cheap) into shared.
//   blockIdx.y in [0,16): build 256 bins each;  ==16: build segment table.
// ---------------------------------------------------------------------------
__global__ void tmo_tables(const float* __restrict__ w,
                           const float* __restrict__ E,
                           const float* __restrict__ f0,
                           const float* __restrict__ Hb) {
    __shared__ float sE[KK];
    __shared__ float sC[KK];
    const int b = blockIdx.x;
    const int part = blockIdx.y;
    const int t = threadIdx.x;

    {
        float acc = f0[t];
        #pragma unroll
        for (int n = 0; n < NBASIS; n++)
            acc = fmaf(Hb[t * NBASIS + n], w[b * NBASIS + n], acc);
        sE[t] = E[t];
        sC[t] = acc;
    }
    __syncthreads();

    if (part == 16) {
        // Segment table
        for (int k = t; k < NSEG; k += blockDim.x) {
            float4 s;
            if (k == 0) {
                s = make_float4(-FLT_MAX, sE[0], 0.0f, sC[0]);
            } else if (k == KK) {
                s = make_float4(sE[KK - 1], FLT_MAX, 0.0f, sC[KK - 1]);
            } else {
                float a = (sC[k] - sC[k - 1]) / (sE[k] - sE[k - 1]);
                s = make_float4(sE[k - 1], sE[k], a, fmaf(-a, sE[k - 1], sC[k - 1]));
            }
            gSegs[b * NSEG + k] = s;
        }
    } else {
        // 256 bins per block
        const int g = part * 256 + t;
        float left  = (float)g       * (1.0f / GBINS);  // exact
        float right = (float)(g + 1) * (1.0f / GBINS);  // exact
        int lo = 0, hi = KK;
        while (lo < hi) {                // k0 = #E <= left
            int mid = (lo + hi) >> 1;
            if (sE[mid] <= left) lo = mid + 1; else hi = mid;
        }
        int k0 = lo;
        float upper = (k0 < KK) ? sE[k0] : FLT_MAX;
        float2 ab;
        if (upper >= right) {
            if (k0 == 0) {
                ab = make_float2(0.0f, sC[0]);
            } else if (k0 == KK) {
                ab = make_float2(0.0f, sC[KK - 1]);
            } else {
                float a = (sC[k0] - sC[k0 - 1]) / (sE[k0] - sE[k0 - 1]);
                ab = make_float2(a, fmaf(-a, sE[k0 - 1], sC[k0 - 1]));
            }
        } else {
            ab = make_float2(__int_as_float(0x7FC00000 | k0), 0.0f);
        }
        gBins[b * GBINS + g] = ab;
    }
}

// ---------------------------------------------------------------------------
// Main kernel: grid (blocks_x, B). 32 KB shared (bins only) -> 7 CTAs/SM.
// Slow path (~6% of lanes) walks the global segment table via __ldg (L1-hot).
// ---------------------------------------------------------------------------
__global__ void __launch_bounds__(256, 7)
tmo_apply(const float* __restrict__ img, float* __restrict__ out) {
    __shared__ float2 sBins[GBINS];   // 32 KB

    const int b = blockIdx.y;
    const float4* __restrict__ segs = gSegs + b * NSEG;

    {
        const float4* src = reinterpret_cast<const float4*>(gBins + (size_t)b * GBINS);
        float4* dst = reinterpret_cast<float4*>(sBins);
        for (int i = threadIdx.x; i < GBINS / 2; i += blockDim.x) dst[i] = src[i];
    }
    __syncthreads();

    const float4* in4  = reinterpret_cast<const float4*>(img + (size_t)b * PIX_PER_BATCH);
    float4*       out4 = reinterpret_cast<float4*>(out + (size_t)b * PIX_PER_BATCH);
    const int nF4 = PIX_PER_BATCH / 4;
    const int stride = gridDim.x * blockDim.x;

    for (int i = blockIdx.x * blockDim.x + threadIdx.x; i < nF4; i += stride) {
        float4 v = in4[i];
        float r[4] = {v.x, v.y, v.z, v.w};
        #pragma unroll
        for (int j = 0; j < 4; j++) {
            float x = r[j];
            int g = (int)(x * (float)GBINS);       // exact bin classification
            g = min(max(g, 0), GBINS - 1);
            float2 ab = sBins[g];
            float y;
            if (!__isnanf(ab.x)) {
                y = fmaf(ab.x, x, ab.y);
            } else {
                int k = __float_as_int(ab.x) & 0xFFFF;
                float4 s = __ldg(&segs[k]);
                while (x >= s.y) { k++; s = __ldg(&segs[k]); }
                y = fmaf(s.z, x, s.w);
            }
            r[j] = fminf(fmaxf(y, 0.0f), 1.0f);
        }
        out4[i] = make_float4(r[0], r[1], r[2], r[3]);
    }
}

extern "C" void kernel_launch(void* const* d_in, const int* in_sizes, int n_in,
                              void* d_out, int out_size) {
    const float* hdr = (const float*)d_in[0];   // [B,C,H,W]
    const float* w   = (const float*)d_in[1];   // [B,NB]
    const float* E   = (const float*)d_in[2];   // [K]
    const float* f0  = (const float*)d_in[3];   // [K]
    const float* Hb  = (const float*)d_in[4];   // [K,NB]
    float* out = (float*)d_out;

    tmo_tables<<<dim3(BB, 17), 256>>>(w, E, f0, Hb);

    dim3 grid(129, BB);   // 1032 blocks = single wave at 7 CTAs/SM
    tmo_apply<<<grid, 256>>>(hdr, out);
}

// round 3
// speedup vs baseline: 1.9092x; 1.9092x over previous
#include <cuda_runtime.h>
#include <cfloat>
#include <cstdint>

#define BB 8
#define CC 3
#define HH 1080
#define WW 1920
#define KK 256
#define NBASIS 25
#define GBINS 2048          // power of two: x*2048.0f is EXACT in fp32
#define NSEG (KK + 1)       // 257 extended segments
#define PIX_PER_BATCH (CC * HH * WW)   // 6,220,800

__device__ float2 gBins[BB * GBINS];   // (a,b) pure bins, or NaN-payload(k0) kinked bins
__device__ float4 gSegs[BB * NSEG];    // (Elo, Ehi, a, b) exact segments

// ---------------------------------------------------------------------------
// Table builder: grid (BB, 9), 256 threads.
//   Every block recomputes the curve (cheap) into shared.
//   blockIdx.y in [0,8): build 256 bins each;  ==8: build segment table.
// ---------------------------------------------------------------------------
__global__ void tmo_tables(const float* __restrict__ w,
                           const float* __restrict__ E,
                           const float* __restrict__ f0,
                           const float* __restrict__ Hb) {
    __shared__ float sE[KK];
    __shared__ float sC[KK];
    const int b = blockIdx.x;
    const int part = blockIdx.y;
    const int t = threadIdx.x;

    {
        float acc = f0[t];
        #pragma unroll
        for (int n = 0; n < NBASIS; n++)
            acc = fmaf(Hb[t * NBASIS + n], w[b * NBASIS + n], acc);
        sE[t] = E[t];
        sC[t] = acc;
    }
    __syncthreads();

    if (part == 8) {
        // Segment table
        for (int k = t; k < NSEG; k += blockDim.x) {
            float4 s;
            if (k == 0) {
                s = make_float4(-FLT_MAX, sE[0], 0.0f, sC[0]);
            } else if (k == KK) {
                s = make_float4(sE[KK - 1], FLT_MAX, 0.0f, sC[KK - 1]);
            } else {
                float a = (sC[k] - sC[k - 1]) / (sE[k] - sE[k - 1]);
                s = make_float4(sE[k - 1], sE[k], a, fmaf(-a, sE[k - 1], sC[k - 1]));
            }
            gSegs[b * NSEG + k] = s;
        }
    } else {
        // 256 bins per block
        const int g = part * 256 + t;
        float left  = (float)g       * (1.0f / GBINS);  // exact
        float right = (float)(g + 1) * (1.0f / GBINS);  // exact
        int lo = 0, hi = KK;
        while (lo < hi) {                // k0 = #E <= left
            int mid = (lo + hi) >> 1;
            if (sE[mid] <= left) lo = mid + 1; else hi = mid;
        }
        int k0 = lo;
        float upper = (k0 < KK) ? sE[k0] : FLT_MAX;
        float2 ab;
        if (upper >= right) {
            if (k0 == 0) {
                ab = make_float2(0.0f, sC[0]);
            } else if (k0 == KK) {
                ab = make_float2(0.0f, sC[KK - 1]);
            } else {
                float a = (sC[k0] - sC[k0 - 1]) / (sE[k0] - sE[k0 - 1]);
                ab = make_float2(a, fmaf(-a, sE[k0 - 1], sC[k0 - 1]));
            }
        } else {
            ab = make_float2(__int_as_float(0x7FC00000 | k0), 0.0f);
        }
        gBins[b * GBINS + g] = ab;
    }
}

// ---------------------------------------------------------------------------
// Main kernel: grid (148, B). ~20.5 KB shared -> 8 CTAs/SM (warp-capped),
// 1184 blocks = exactly one wave. Slow path (~12% of lanes) walks the
// shared-memory segment table (LDS, latency-tolerant).
// ---------------------------------------------------------------------------
__global__ void __launch_bounds__(256, 8)
tmo_apply(const float* __restrict__ img, float* __restrict__ out) {
    __shared__ float2 sBins[GBINS];   // 16 KB
    __shared__ float4 sSegs[NSEG];    // ~4.1 KB

    const int b = blockIdx.y;

    {
        const float4* src = reinterpret_cast<const float4*>(gBins + (size_t)b * GBINS);
        float4* dst = reinterpret_cast<float4*>(sBins);
        for (int i = threadIdx.x; i < GBINS / 2; i += blockDim.x) dst[i] = src[i];
        for (int i = threadIdx.x; i < NSEG; i += blockDim.x)
            sSegs[i] = gSegs[b * NSEG + i];
    }
    __syncthreads();

    const float4* in4  = reinterpret_cast<const float4*>(img + (size_t)b * PIX_PER_BATCH);
    float4*       out4 = reinterpret_cast<float4*>(out + (size_t)b * PIX_PER_BATCH);
    const int nF4 = PIX_PER_BATCH / 4;
    const int stride = gridDim.x * blockDim.x;

    for (int i = blockIdx.x * blockDim.x + threadIdx.x; i < nF4; i += stride) {
        float4 v = in4[i];
        float r[4] = {v.x, v.y, v.z, v.w};
        #pragma unroll
        for (int j = 0; j < 4; j++) {
            float x = r[j];
            int g = (int)(x * (float)GBINS);       // exact bin classification
            g = min(max(g, 0), GBINS - 1);
            float2 ab = sBins[g];
            float y;
            if (!__isnanf(ab.x)) {
                y = fmaf(ab.x, x, ab.y);
            } else {
                int k = __float_as_int(ab.x) & 0xFFFF;
                float4 s = sSegs[k];
                while (x >= s.y) { k++; s = sSegs[k]; }
                y = fmaf(s.z, x, s.w);
            }
            r[j] = fminf(fmaxf(y, 0.0f), 1.0f);
        }
        out4[i] = make_float4(r[0], r[1], r[2], r[3]);
    }
}

extern "C" void kernel_launch(void* const* d_in, const int* in_sizes, int n_in,
                              void* d_out, int out_size) {
    const float* hdr = (const float*)d_in[0];   // [B,C,H,W]
    const float* w   = (const float*)d_in[1];   // [B,NB]
    const float* E   = (const float*)d_in[2];   // [K]
    const float* f0  = (const float*)d_in[3];   // [K]
    const float* Hb  = (const float*)d_in[4];   // [K,NB]
    float* out = (float*)d_out;

    tmo_tables<<<dim3(BB, 9), 256>>>(w, E, f0, Hb);

    dim3 grid(148, BB);   // 1184 blocks = single wave at 8 CTAs/SM
    tmo_apply<<<grid, 256>>>(hdr, out);
}

// round 4
// speedup vs baseline: 2.0888x; 1.0941x over previous
#include <cuda_runtime.h>
#include <cuda_fp16.h>
#include <cfloat>
#include <cstdint>

#define BB 8
#define CC 3
#define HH 1080
#define WW 1920
#define KK 256
#define NBASIS 25
#define GBINS 4096          // power of two: x*4096.0f and frac are EXACT in fp32
#define NSEG (KK + 1)       // 257 extended segments
#define PIX_PER_BATCH (CC * HH * WW)   // 6,220,800

// Bin entry (uint32): pure bin  -> lo16 = half(y_left), hi16 = half(y_right)
//                     kinked    -> lo16 = 0x7FFF (NaN sentinel), hi16 = k0
__device__ uint32_t gBinsU[BB * GBINS];
__device__ float4   gSegs[BB * NSEG];   // (Elo, Ehi, a, b) exact segments

// ---------------------------------------------------------------------------
// Table builder: grid (BB, 17), 256 threads.
//   Every block recomputes the curve (cheap) into shared.
//   blockIdx.y in [0,16): build 256 bins each;  ==16: build segment table.
// ---------------------------------------------------------------------------
__global__ void tmo_tables(const float* __restrict__ w,
                           const float* __restrict__ E,
                           const float* __restrict__ f0,
                           const float* __restrict__ Hb) {
    __shared__ float sE[KK];
    __shared__ float sC[KK];
    const int b = blockIdx.x;
    const int part = blockIdx.y;
    const int t = threadIdx.x;

    {
        float acc = f0[t];
        #pragma unroll
        for (int n = 0; n < NBASIS; n++)
            acc = fmaf(Hb[t * NBASIS + n], w[b * NBASIS + n], acc);
        sE[t] = E[t];
        sC[t] = acc;
    }
    __syncthreads();

    if (part == 16) {
        // Exact segment table (fp32), used by the slow path
        for (int k = t; k < NSEG; k += blockDim.x) {
            float4 s;
            if (k == 0) {
                s = make_float4(-FLT_MAX, sE[0], 0.0f, sC[0]);
            } else if (k == KK) {
                s = make_float4(sE[KK - 1], FLT_MAX, 0.0f, sC[KK - 1]);
            } else {
                float a = (sC[k] - sC[k - 1]) / (sE[k] - sE[k - 1]);
                s = make_float4(sE[k - 1], sE[k], a, fmaf(-a, sE[k - 1], sC[k - 1]));
            }
            gSegs[b * NSEG + k] = s;
        }
    } else {
        // 256 bins per block
        const int g = part * 256 + t;
        float left  = (float)g       * (1.0f / GBINS);  // exact
        float right = (float)(g + 1) * (1.0f / GBINS);  // exact
        int lo = 0, hi = KK;
        while (lo < hi) {                // k0 = #E <= left
            int mid = (lo + hi) >> 1;
            if (sE[mid] <= left) lo = mid + 1; else hi = mid;
        }
        int k0 = lo;
        float upper = (k0 < KK) ? sE[k0] : FLT_MAX;
        uint32_t u;
        if (upper >= right) {
            // Pure bin: endpoint values of the containing segment, fp16
            float yl, yr;
            if (k0 == 0) {
                yl = yr = sC[0];
            } else if (k0 == KK) {
                yl = yr = sC[KK - 1];
            } else {
                float a = (sC[k0] - sC[k0 - 1]) / (sE[k0] - sE[k0 - 1]);
                float bint = fmaf(-a, sE[k0 - 1], sC[k0 - 1]);
                yl = fmaf(a, left,  bint);
                yr = fmaf(a, right, bint);
            }
            uint16_t hl = __half_as_ushort(__float2half_rn(yl));
            uint16_t hr = __half_as_ushort(__float2half_rn(yr));
            if (hl == 0x7FFFu) hl = 0x7FFEu;  // paranoia: avoid sentinel collision
            u = ((uint32_t)hr << 16) | hl;
        } else {
            u = ((uint32_t)k0 << 16) | 0x7FFFu;   // kinked bin sentinel
        }
        gBinsU[b * GBINS + g] = u;
    }
}

// ---------------------------------------------------------------------------
// Main kernel: grid (148, B). ~20.6 KB shared -> 8 CTAs/SM, 1184 blocks =
// exactly one wave. Fast path: one LDS.32 + lerp. Slow path (~6% of lanes):
// exact fp32 segment walk in shared memory.
// ---------------------------------------------------------------------------
__global__ void __launch_bounds__(256, 8)
tmo_apply(const float* __restrict__ img, float* __restrict__ out) {
    __shared__ uint32_t sBins[GBINS];   // 16 KB
    __shared__ float4   sSegs[NSEG];    // ~4.1 KB

    const int b = blockIdx.y;

    {
        const uint4* src = reinterpret_cast<const uint4*>(gBinsU + (size_t)b * GBINS);
        uint4* dst = reinterpret_cast<uint4*>(sBins);
        for (int i = threadIdx.x; i < GBINS / 4; i += blockDim.x) dst[i] = src[i];
        for (int i = threadIdx.x; i < NSEG; i += blockDim.x)
            sSegs[i] = gSegs[b * NSEG + i];
    }
    __syncthreads();

    const float4* in4  = reinterpret_cast<const float4*>(img + (size_t)b * PIX_PER_BATCH);
    float4*       out4 = reinterpret_cast<float4*>(out + (size_t)b * PIX_PER_BATCH);
    const int nF4 = PIX_PER_BATCH / 4;
    const int stride = gridDim.x * blockDim.x;

    for (int i = blockIdx.x * blockDim.x + threadIdx.x; i < nF4; i += stride) {
        float4 v = in4[i];
        float r[4] = {v.x, v.y, v.z, v.w};
        #pragma unroll
        for (int j = 0; j < 4; j++) {
            float x = r[j];
            float xg = x * (float)GBINS;           // exact (power-of-two scale)
            int g = (int)xg;
            g = min(max(g, 0), GBINS - 1);
            uint32_t u = sBins[g];
            float y;
            if ((u & 0xFFFFu) != 0x7FFFu) {
                float2 yy = __half22float2(*reinterpret_cast<const __half2*>(&u));
                float frac = xg - (float)g;        // exact
                y = fmaf(yy.y - yy.x, frac, yy.x);
            } else {
                int k = (int)(u >> 16);
                float4 s = sSegs[k];
                while (x >= s.y) { k++; s = sSegs[k]; }
                y = fmaf(s.z, x, s.w);
            }
            r[j] = fminf(fmaxf(y, 0.0f), 1.0f);
        }
        out4[i] = make_float4(r[0], r[1], r[2], r[3]);
    }
}

extern "C" void kernel_launch(void* const* d_in, const int* in_sizes, int n_in,
                              void* d_out, int out_size) {
    const float* hdr = (const float*)d_in[0];   // [B,C,H,W]
    const float* w   = (const float*)d_in[1];   // [B,NB]
    const float* E   = (const float*)d_in[2];   // [K]
    const float* f0  = (const float*)d_in[3];   // [K]
    const float* Hb  = (const float*)d_in[4];   // [K,NB]
    float* out = (float*)d_out;

    tmo_tables<<<dim3(BB, 17), 256>>>(w, E, f0, Hb);

    dim3 grid(148, BB);   // 1184 blocks = single wave at 8 CTAs/SM
    tmo_apply<<<grid, 256>>>(hdr, out);
}